// round 4
// baseline (speedup 1.0000x reference)
#include <cuda_runtime.h>
#include <cstdint>

// VectorQuantizer: input (16, 64, 8192) fp32, codebook (1024, 64) fp32
// score(n,k) = 0.5*||e_k||^2 - x_n . e_k   (argmin-equivalent to ||x - e||^2)
//
// fp32x2 packed-FMA kernel. Lane pairs split the D=64 row (even lane: dims
// 0-31, odd: 32-63), 4 tokens per thread -> 8 LDS.128 : 64 FFMA2 per warp
// per code. Partial dots merged with shfl.bfly. cp.async double-buffered
// codebook chunks.

#define Dd 64
#define Kk 1024
#define Bb 16
#define Tt 8192
#define Nn (Bb * Tt)            // 131072 tokens
#define TPB 128
#define TOKT 4                  // tokens per thread (pair-shared)
#define TOK_PER_CTA 256         // (TPB/2) pairs * 4 tokens
#define CK 64                   // codes per smem chunk (64*64*4 = 16 KB)
#define NCHUNK (Kk / CK)        // 16

__device__ float g_half[Kk];

// ---- packed f32x2 helpers ----
__device__ __forceinline__ unsigned long long pk2(float a, float b) {
    unsigned long long r;
    asm("mov.b64 %0, {%1, %2};" : "=l"(r) : "f"(a), "f"(b));
    return r;
}
__device__ __forceinline__ void fma2(unsigned long long& acc,
                                     unsigned long long a, unsigned long long b) {
    asm("fma.rn.f32x2 %0, %1, %2, %0;" : "+l"(acc) : "l"(a), "l"(b));
}
__device__ __forceinline__ unsigned long long add2(unsigned long long a,
                                                   unsigned long long b) {
    unsigned long long r;
    asm("add.rn.f32x2 %0, %1, %2;" : "=l"(r) : "l"(a), "l"(b));
    return r;
}
__device__ __forceinline__ float hsum2(unsigned long long v) {
    float lo, hi;
    asm("mov.b64 {%0, %1}, %2;" : "=f"(lo), "=f"(hi) : "l"(v));
    return lo + hi;
}

// ---- cp.async helpers ----
__device__ __forceinline__ void cp16(uint32_t dst, const float* src) {
    uint64_t g = __cvta_generic_to_global((void*)src);
    asm volatile("cp.async.cg.shared.global [%0], [%1], 16;" :: "r"(dst), "l"(g) : "memory");
}
__device__ __forceinline__ void cp_commit() { asm volatile("cp.async.commit_group;" ::: "memory"); }
template <int N>
__device__ __forceinline__ void cp_wait() { asm volatile("cp.async.wait_group %0;" :: "n"(N) : "memory"); }

__device__ __forceinline__ uint32_t s2u(const void* p) {
    uint32_t a;
    asm("{ .reg .u64 t; cvta.to.shared.u64 t, %1; cvt.u32.u64 %0, t; }" : "=r"(a) : "l"(p));
    return a;
}

// Precompute 0.5*||e_k||^2.
__global__ void vq_pre(const float* __restrict__ cb) {
    int k = blockIdx.x * blockDim.x + threadIdx.x;
    if (k >= Kk) return;
    const float4* row = reinterpret_cast<const float4*>(cb + k * Dd);
    float s = 0.f;
#pragma unroll
    for (int i = 0; i < Dd / 4; i++) {
        float4 v = row[i];
        s += v.x * v.x + v.y * v.y + v.z * v.z + v.w * v.w;
    }
    g_half[k] = 0.5f * s;
}

// smem chunk layout: code row = 256B. 16B slot g (0..15) of the original row
// maps to offset row*256 + (g&7)*32 + (g>>3)*16  (halves interleaved 16B so
// even/odd lane reads hit disjoint bank groups).
__global__ __launch_bounds__(TPB, 3)
void vq_main(const float* __restrict__ input, const float* __restrict__ cb,
             float* __restrict__ out, float* __restrict__ out_idx) {
    __shared__ float sCode[2][CK * Dd];   // 2 x 16 KB
    __shared__ float sHalf[Kk];           // 4 KB

    const int tid  = threadIdx.x;
    const int half = tid & 1;             // 0: dims 0-31, 1: dims 32-63
    const int p    = tid >> 1;            // pair id 0..63
    const int tile = blockIdx.x;          // 0..511
    const int b    = tile >> 5;           // 32 tiles per batch
    const int tb   = (tile & 31) * TOK_PER_CTA;  // base time index

    const uint32_t sc0 = s2u(&sCode[0][0]);
    const uint32_t sc1 = s2u(&sCode[1][0]);

    // ---- prefetch codebook chunk 0 (interleaved-half layout) ----
#pragma unroll
    for (int s = 0; s < (CK * 16) / TPB; s++) {   // 8 slots per thread
        int idx = tid + s * TPB;
        int row = idx >> 4, g = idx & 15;
        uint32_t dst = sc0 + row * 256 + (g & 7) * 32 + (g >> 3) * 16;
        cp16(dst, cb + row * Dd + g * 4);
    }
    cp_commit();

    // ---- load 4 tokens, this lane's half of D, packed along d ----
    // token j lives at time t = tb + p + j*64
    unsigned long long x[TOKT][16];
    {
        const float* inb = input + (size_t)b * Dd * Tt + (size_t)(half * 32) * Tt + tb + p;
#pragma unroll
        for (int j = 0; j < TOKT; j++) {
            const float* pj = inb + j * 64;
#pragma unroll
            for (int i = 0; i < 16; i++) {
                float a = pj[(size_t)(2 * i) * Tt];
                float c = pj[(size_t)(2 * i + 1) * Tt];
                x[j][i] = pk2(a, c);
            }
        }
    }

#pragma unroll
    for (int i = tid; i < Kk; i += TPB) sHalf[i] = g_half[i];

    float best[TOKT];
    int   bidx[TOKT];
#pragma unroll
    for (int j = 0; j < TOKT; j++) { best[j] = 3.4e38f; bidx[j] = 0; }

    const int hoff = half * 16;           // byte offset selecting this lane's half

    for (int c = 0; c < NCHUNK; c++) {
        // prefetch chunk c+1 into the other buffer
        if (c + 1 < NCHUNK) {
            const uint32_t nxt = (c & 1) ? sc0 : sc1;
            const float* src = cb + (size_t)(c + 1) * CK * Dd;
#pragma unroll
            for (int s = 0; s < (CK * 16) / TPB; s++) {
                int idx = tid + s * TPB;
                int row = idx >> 4, g = idx & 15;
                cp16(nxt + row * 256 + (g & 7) * 32 + (g >> 3) * 16, src + row * Dd + g * 4);
            }
            cp_commit();
            cp_wait<1>();                 // chunk c complete; c+1 in flight
        } else {
            cp_wait<0>();
        }
        __syncthreads();

        const char* buf = (const char*)((c & 1) ? &sCode[1][0] : &sCode[0][0]);
        const int kbase = c * CK;
#pragma unroll 2
        for (int k = 0; k < CK; k++) {
            const char* rowp = buf + k * 256 + hoff;
            unsigned long long a00 = 0, a01 = 0, a10 = 0, a11 = 0;
            unsigned long long a20 = 0, a21 = 0, a30 = 0, a31 = 0;
#pragma unroll
            for (int j = 0; j < 8; j++) {
                // slot j of this lane's half: 2 packed e-pairs (4 dims)
                ulonglong2 e = *reinterpret_cast<const ulonglong2*>(rowp + j * 32);
                if (j & 1) {
                    fma2(a01, x[0][2 * j], e.x); fma2(a01, x[0][2 * j + 1], e.y);
                    fma2(a11, x[1][2 * j], e.x); fma2(a11, x[1][2 * j + 1], e.y);
                    fma2(a21, x[2][2 * j], e.x); fma2(a21, x[2][2 * j + 1], e.y);
                    fma2(a31, x[3][2 * j], e.x); fma2(a31, x[3][2 * j + 1], e.y);
                } else {
                    fma2(a00, x[0][2 * j], e.x); fma2(a00, x[0][2 * j + 1], e.y);
                    fma2(a10, x[1][2 * j], e.x); fma2(a10, x[1][2 * j + 1], e.y);
                    fma2(a20, x[2][2 * j], e.x); fma2(a20, x[2][2 * j + 1], e.y);
                    fma2(a30, x[3][2 * j], e.x); fma2(a30, x[3][2 * j + 1], e.y);
                }
            }
            const int kk = kbase + k;
            const float hs = sHalf[kk];
            float p0 = hsum2(add2(a00, a01));
            float p1 = hsum2(add2(a10, a11));
            float p2 = hsum2(add2(a20, a21));
            float p3 = hsum2(add2(a30, a31));
            // merge with partner lane's half (commutative add -> identical in pair)
            float q0 = __shfl_xor_sync(0xffffffffu, p0, 1);
            float q1 = __shfl_xor_sync(0xffffffffu, p1, 1);
            float q2 = __shfl_xor_sync(0xffffffffu, p2, 1);
            float q3 = __shfl_xor_sync(0xffffffffu, p3, 1);
            float s0 = hs - (p0 + q0);
            float s1 = hs - (p1 + q1);
            float s2 = hs - (p2 + q2);
            float s3 = hs - (p3 + q3);
            if (s0 < best[0]) { best[0] = s0; bidx[0] = kk; }
            if (s1 < best[1]) { best[1] = s1; bidx[1] = kk; }
            if (s2 < best[2]) { best[2] = s2; bidx[2] = kk; }
            if (s3 < best[3]) { best[3] = s3; bidx[3] = kk; }
        }
        __syncthreads();   // protect buffer before next prefetch overwrites it
    }

    // ---- outputs: even lane writes tokens 0,1; odd lane writes 2,3 ----
    const int jlo = half * 2;
#pragma unroll
    for (int jj = 0; jj < 2; jj++) {
        const int j = jlo + jj;
        const int t = tb + p + j * 64;
        float* ob = out + (size_t)b * Dd * Tt + t;
        const float4* cv = reinterpret_cast<const float4*>(cb + (size_t)bidx[j] * Dd);
#pragma unroll
        for (int i = 0; i < Dd / 4; i++) {
            float4 v = cv[i];
            ob[(size_t)(4 * i + 0) * Tt] = v.x;
            ob[(size_t)(4 * i + 1) * Tt] = v.y;
            ob[(size_t)(4 * i + 2) * Tt] = v.z;
            ob[(size_t)(4 * i + 3) * Tt] = v.w;
        }
        if (out_idx != nullptr) {
            out_idx[(size_t)b * Tt + t] = (float)bidx[j];
        }
    }
}

extern "C" void kernel_launch(void* const* d_in, const int* in_sizes, int n_in,
                              void* d_out, int out_size) {
    const float* input = (const float*)d_in[0];   // (16, 64, 8192) fp32
    const float* cb    = (const float*)d_in[1];   // (1024, 64) fp32
    float* out = (float*)d_out;

    float* out_idx = nullptr;
    if (out_size >= (int)((long)Nn * Dd + Nn)) out_idx = out + (long)Nn * Dd;

    vq_pre<<<(Kk + 127) / 128, 128>>>(cb);
    vq_main<<<Nn / TOK_PER_CTA, TPB>>>(input, cb, out, out_idx);
}